// round 3
// baseline (speedup 1.0000x reference)
#include <cuda_runtime.h>
#include <cstdint>

#define NUM_BLOCKS 592           // 148 SMs * 4 CTAs — exactly one wave
#define NUM_THREADS 512

// Per-block partials — fully overwritten every launch, no init needed.
__device__ float        g_partial_sum[NUM_BLOCKS];
__device__ unsigned int g_partial_cnt[NUM_BLOCKS];
// atomicInc with wrap (gridDim-1) self-resets to 0 each launch -> graph-safe.
__device__ unsigned int g_retire_count;

__global__ void __launch_bounds__(NUM_THREADS, 4) dlwm_fused_kernel(
    const float4* __restrict__ out,
    const float4* __restrict__ lbl0,
    const float4* __restrict__ lbl1,
    float* __restrict__ d_out,
    int n4)
{
    float acc = 0.0f;
    unsigned int cnt = 0;

    const int stride = gridDim.x * blockDim.x;
    int i = blockIdx.x * blockDim.x + threadIdx.x;

    // 2x-unrolled grid-stride loop; 6 streaming 128-bit loads in flight.
    for (; i + stride < n4; i += 2 * stride) {
        float4 o0 = __ldcs(out  + i);
        float4 a0 = __ldcs(lbl0 + i);
        float4 b0 = __ldcs(lbl1 + i);
        float4 o1 = __ldcs(out  + i + stride);
        float4 a1 = __ldcs(lbl0 + i + stride);
        float4 b1 = __ldcs(lbl1 + i + stride);

        acc += fabsf(o0.x - a0.x) * b0.x;
        acc += fabsf(o0.y - a0.y) * b0.y;
        acc += fabsf(o0.z - a0.z) * b0.z;
        acc += fabsf(o0.w - a0.w) * b0.w;
        acc += fabsf(o1.x - a1.x) * b1.x;
        acc += fabsf(o1.y - a1.y) * b1.y;
        acc += fabsf(o1.z - a1.z) * b1.z;
        acc += fabsf(o1.w - a1.w) * b1.w;

        cnt += (a0.x != 0.0f) + (a0.y != 0.0f) + (a0.z != 0.0f) + (a0.w != 0.0f);
        cnt += (a1.x != 0.0f) + (a1.y != 0.0f) + (a1.z != 0.0f) + (a1.w != 0.0f);
    }
    for (; i < n4; i += stride) {
        float4 o = __ldcs(out  + i);
        float4 a = __ldcs(lbl0 + i);
        float4 b = __ldcs(lbl1 + i);
        acc += fabsf(o.x - a.x) * b.x;
        acc += fabsf(o.y - a.y) * b.y;
        acc += fabsf(o.z - a.z) * b.z;
        acc += fabsf(o.w - a.w) * b.w;
        cnt += (a.x != 0.0f) + (a.y != 0.0f) + (a.z != 0.0f) + (a.w != 0.0f);
    }

    // ---- intra-block reduction ----
    #pragma unroll
    for (int off = 16; off > 0; off >>= 1) {
        acc += __shfl_down_sync(0xFFFFFFFFu, acc, off);
        cnt += __shfl_down_sync(0xFFFFFFFFu, cnt, off);
    }

    __shared__ float        s_acc[16];
    __shared__ unsigned int s_cnt[16];
    __shared__ bool         s_is_last;
    const int lane = threadIdx.x & 31;
    const int wid  = threadIdx.x >> 5;
    if (lane == 0) { s_acc[wid] = acc; s_cnt[wid] = cnt; }
    __syncthreads();

    if (wid == 0) {
        acc = (lane < (NUM_THREADS / 32)) ? s_acc[lane] : 0.0f;
        cnt = (lane < (NUM_THREADS / 32)) ? s_cnt[lane] : 0u;
        #pragma unroll
        for (int off = 8; off > 0; off >>= 1) {
            acc += __shfl_down_sync(0xFFFFFFFFu, acc, off);
            cnt += __shfl_down_sync(0xFFFFFFFFu, cnt, off);
        }
        if (lane == 0) {
            g_partial_sum[blockIdx.x] = acc;
            g_partial_cnt[blockIdx.x] = cnt;
            __threadfence();
            unsigned int ticket = atomicInc(&g_retire_count, gridDim.x - 1);
            s_is_last = (ticket == gridDim.x - 1);
        }
    }
    __syncthreads();

    // ---- last block reduces partials (L2-resident) and writes the scalar ----
    if (s_is_last) {
        float        fsum = 0.0f;
        unsigned int csum = 0;
        for (int j = threadIdx.x; j < gridDim.x; j += blockDim.x) {
            fsum += g_partial_sum[j];
            csum += g_partial_cnt[j];
        }
        #pragma unroll
        for (int off = 16; off > 0; off >>= 1) {
            fsum += __shfl_down_sync(0xFFFFFFFFu, fsum, off);
            csum += __shfl_down_sync(0xFFFFFFFFu, csum, off);
        }
        if (lane == 0) { s_acc[wid] = fsum; s_cnt[wid] = csum; }
        __syncthreads();
        if (wid == 0) {
            fsum = (lane < (NUM_THREADS / 32)) ? s_acc[lane] : 0.0f;
            csum = (lane < (NUM_THREADS / 32)) ? s_cnt[lane] : 0u;
            #pragma unroll
            for (int off = 8; off > 0; off >>= 1) {
                fsum += __shfl_down_sync(0xFFFFFFFFu, fsum, off);
                csum += __shfl_down_sync(0xFFFFFFFFu, csum, off);
            }
            if (lane == 0) {
                d_out[0] = (csum == 0u) ? 0.0f : (fsum / (float)csum);
            }
        }
    }
}

extern "C" void kernel_launch(void* const* d_in, const int* in_sizes, int n_in,
                              void* d_out, int out_size)
{
    const float4* out_t = (const float4*)d_in[0];
    const float4* lbl0  = (const float4*)d_in[1];
    const float4* lbl1  = (const float4*)d_in[2];
    const int n  = in_sizes[0];   // 15,728,640 (divisible by 4)
    const int n4 = n >> 2;

    int blocks = NUM_BLOCKS;
    int max_blocks = (n4 + NUM_THREADS - 1) / NUM_THREADS;
    if (blocks > max_blocks) blocks = max_blocks;

    dlwm_fused_kernel<<<blocks, NUM_THREADS>>>(out_t, lbl0, lbl1, (float*)d_out, n4);
}

// round 4
// speedup vs baseline: 1.0615x; 1.0615x over previous
#include <cuda_runtime.h>
#include <cstdint>

#define NUM_BLOCKS 592           // 148 SMs * 4 CTAs — one wave
#define NUM_THREADS 512

// Scalar accumulators. Zero at module load; the LAST block of every launch
// resets them to zero after consuming them, so every graph replay starts
// from a clean state with no init kernel.
__device__ float        g_sum;
__device__ unsigned int g_cnt;
__device__ unsigned int g_ticket;

__global__ void __launch_bounds__(NUM_THREADS, 4) dlwm_fused_kernel(
    const float4* __restrict__ out,
    const float4* __restrict__ lbl0,
    const float4* __restrict__ lbl1,
    float* __restrict__ d_out,
    int n4)
{
    float acc = 0.0f;
    unsigned int cnt = 0;

    const int stride = gridDim.x * blockDim.x;
    int i = blockIdx.x * blockDim.x + threadIdx.x;

    // 2x-unrolled grid-stride loop; 6 x 128-bit loads in flight per iter.
    for (; i + stride < n4; i += 2 * stride) {
        float4 o0 = __ldg(out  + i);
        float4 a0 = __ldg(lbl0 + i);
        float4 b0 = __ldg(lbl1 + i);
        float4 o1 = __ldg(out  + i + stride);
        float4 a1 = __ldg(lbl0 + i + stride);
        float4 b1 = __ldg(lbl1 + i + stride);

        acc += fabsf(o0.x - a0.x) * b0.x;
        acc += fabsf(o0.y - a0.y) * b0.y;
        acc += fabsf(o0.z - a0.z) * b0.z;
        acc += fabsf(o0.w - a0.w) * b0.w;
        acc += fabsf(o1.x - a1.x) * b1.x;
        acc += fabsf(o1.y - a1.y) * b1.y;
        acc += fabsf(o1.z - a1.z) * b1.z;
        acc += fabsf(o1.w - a1.w) * b1.w;

        cnt += (a0.x != 0.0f) + (a0.y != 0.0f) + (a0.z != 0.0f) + (a0.w != 0.0f);
        cnt += (a1.x != 0.0f) + (a1.y != 0.0f) + (a1.z != 0.0f) + (a1.w != 0.0f);
    }
    for (; i < n4; i += stride) {
        float4 o = __ldg(out  + i);
        float4 a = __ldg(lbl0 + i);
        float4 b = __ldg(lbl1 + i);
        acc += fabsf(o.x - a.x) * b.x;
        acc += fabsf(o.y - a.y) * b.y;
        acc += fabsf(o.z - a.z) * b.z;
        acc += fabsf(o.w - a.w) * b.w;
        cnt += (a.x != 0.0f) + (a.y != 0.0f) + (a.z != 0.0f) + (a.w != 0.0f);
    }

    // ---- intra-block reduction ----
    #pragma unroll
    for (int off = 16; off > 0; off >>= 1) {
        acc += __shfl_down_sync(0xFFFFFFFFu, acc, off);
        cnt += __shfl_down_sync(0xFFFFFFFFu, cnt, off);
    }

    __shared__ float        s_acc[NUM_THREADS / 32];
    __shared__ unsigned int s_cnt[NUM_THREADS / 32];
    const int lane = threadIdx.x & 31;
    const int wid  = threadIdx.x >> 5;
    if (lane == 0) { s_acc[wid] = acc; s_cnt[wid] = cnt; }
    __syncthreads();

    if (wid == 0) {
        acc = (lane < (NUM_THREADS / 32)) ? s_acc[lane] : 0.0f;
        cnt = (lane < (NUM_THREADS / 32)) ? s_cnt[lane] : 0u;
        #pragma unroll
        for (int off = 8; off > 0; off >>= 1) {
            acc += __shfl_down_sync(0xFFFFFFFFu, acc, off);
            cnt += __shfl_down_sync(0xFFFFFFFFu, cnt, off);
        }
        if (lane == 0) {
            // Relaxed scalar accumulation — no fence, no L1 flush.
            atomicAdd(&g_sum, acc);
            atomicAdd(&g_cnt, cnt);

            // acq_rel ticket: release orders the adds above; acquire lets
            // the last arriver observe every block's adds. No CCTL.IVALL.
            unsigned int ticket;
            asm volatile(
                "atom.acq_rel.gpu.global.add.u32 %0, [%1], %2;"
                : "=r"(ticket)
                : "l"(&g_ticket), "r"(1u)
                : "memory");

            if (ticket == gridDim.x - 1) {
                // Atomic reads (L2-coherent, post-acquire).
                float        fsum = atomicAdd(&g_sum, 0.0f);
                unsigned int csum = atomicAdd(&g_cnt, 0u);
                d_out[0] = (csum == 0u) ? 0.0f : (fsum / (float)csum);
                // Self-clean for the next graph replay.
                atomicExch(&g_sum, 0.0f);
                atomicExch(&g_cnt, 0u);
                atomicExch(&g_ticket, 0u);
            }
        }
    }
}

extern "C" void kernel_launch(void* const* d_in, const int* in_sizes, int n_in,
                              void* d_out, int out_size)
{
    const float4* out_t = (const float4*)d_in[0];
    const float4* lbl0  = (const float4*)d_in[1];
    const float4* lbl1  = (const float4*)d_in[2];
    const int n  = in_sizes[0];   // 15,728,640 (divisible by 4)
    const int n4 = n >> 2;

    int blocks = NUM_BLOCKS;
    int max_blocks = (n4 + NUM_THREADS - 1) / NUM_THREADS;
    if (blocks > max_blocks) blocks = max_blocks;

    dlwm_fused_kernel<<<blocks, NUM_THREADS>>>(out_t, lbl0, lbl1, (float*)d_out, n4);
}

// round 5
// speedup vs baseline: 1.0626x; 1.0010x over previous
#include <cuda_runtime.h>
#include <cstdint>

#define NUM_SMS     152          // GB300
#define CTAS_PER_SM 2            // oe=2 keeps oe*MLP_p1 under the L1tex-queue knee
#define NUM_BLOCKS  (NUM_SMS * CTAS_PER_SM)   // 304 — one uniform wave
#define NUM_THREADS 512

// Scalar accumulators. Zero at module load; the LAST arriver of every launch
// resets them after consuming them -> deterministic across graph replays,
// no init kernel needed.
__device__ float        g_sum;
__device__ unsigned int g_cnt;
__device__ unsigned int g_ticket;

__global__ void __launch_bounds__(NUM_THREADS, CTAS_PER_SM) dlwm_fused_kernel(
    const float4* __restrict__ out,
    const float4* __restrict__ lbl0,
    const float4* __restrict__ lbl1,
    float* __restrict__ d_out,
    int n4)
{
    float acc = 0.0f;
    unsigned int cnt = 0;

    const int stride = gridDim.x * blockDim.x;
    int i = blockIdx.x * blockDim.x + threadIdx.x;

    // 4x-unrolled grid-stride loop: 12 x 128-bit loads in flight per iter.
    for (; i + 3 * stride < n4; i += 4 * stride) {
        float4 o0 = __ldg(out  + i);
        float4 a0 = __ldg(lbl0 + i);
        float4 b0 = __ldg(lbl1 + i);
        float4 o1 = __ldg(out  + i + stride);
        float4 a1 = __ldg(lbl0 + i + stride);
        float4 b1 = __ldg(lbl1 + i + stride);
        float4 o2 = __ldg(out  + i + 2 * stride);
        float4 a2 = __ldg(lbl0 + i + 2 * stride);
        float4 b2 = __ldg(lbl1 + i + 2 * stride);
        float4 o3 = __ldg(out  + i + 3 * stride);
        float4 a3 = __ldg(lbl0 + i + 3 * stride);
        float4 b3 = __ldg(lbl1 + i + 3 * stride);

        acc += fabsf(o0.x - a0.x) * b0.x;
        acc += fabsf(o0.y - a0.y) * b0.y;
        acc += fabsf(o0.z - a0.z) * b0.z;
        acc += fabsf(o0.w - a0.w) * b0.w;
        cnt += (a0.x != 0.0f) + (a0.y != 0.0f) + (a0.z != 0.0f) + (a0.w != 0.0f);

        acc += fabsf(o1.x - a1.x) * b1.x;
        acc += fabsf(o1.y - a1.y) * b1.y;
        acc += fabsf(o1.z - a1.z) * b1.z;
        acc += fabsf(o1.w - a1.w) * b1.w;
        cnt += (a1.x != 0.0f) + (a1.y != 0.0f) + (a1.z != 0.0f) + (a1.w != 0.0f);

        acc += fabsf(o2.x - a2.x) * b2.x;
        acc += fabsf(o2.y - a2.y) * b2.y;
        acc += fabsf(o2.z - a2.z) * b2.z;
        acc += fabsf(o2.w - a2.w) * b2.w;
        cnt += (a2.x != 0.0f) + (a2.y != 0.0f) + (a2.z != 0.0f) + (a2.w != 0.0f);

        acc += fabsf(o3.x - a3.x) * b3.x;
        acc += fabsf(o3.y - a3.y) * b3.y;
        acc += fabsf(o3.z - a3.z) * b3.z;
        acc += fabsf(o3.w - a3.w) * b3.w;
        cnt += (a3.x != 0.0f) + (a3.y != 0.0f) + (a3.z != 0.0f) + (a3.w != 0.0f);
    }
    // Tail: up to 3 strides remain.
    for (; i < n4; i += stride) {
        float4 o = __ldg(out  + i);
        float4 a = __ldg(lbl0 + i);
        float4 b = __ldg(lbl1 + i);
        acc += fabsf(o.x - a.x) * b.x;
        acc += fabsf(o.y - a.y) * b.y;
        acc += fabsf(o.z - a.z) * b.z;
        acc += fabsf(o.w - a.w) * b.w;
        cnt += (a.x != 0.0f) + (a.y != 0.0f) + (a.z != 0.0f) + (a.w != 0.0f);
    }

    // ---- intra-block reduction ----
    #pragma unroll
    for (int off = 16; off > 0; off >>= 1) {
        acc += __shfl_down_sync(0xFFFFFFFFu, acc, off);
        cnt += __shfl_down_sync(0xFFFFFFFFu, cnt, off);
    }

    __shared__ float        s_acc[NUM_THREADS / 32];
    __shared__ unsigned int s_cnt[NUM_THREADS / 32];
    const int lane = threadIdx.x & 31;
    const int wid  = threadIdx.x >> 5;
    if (lane == 0) { s_acc[wid] = acc; s_cnt[wid] = cnt; }
    __syncthreads();

    if (wid == 0) {
        acc = (lane < (NUM_THREADS / 32)) ? s_acc[lane] : 0.0f;
        cnt = (lane < (NUM_THREADS / 32)) ? s_cnt[lane] : 0u;
        #pragma unroll
        for (int off = 8; off > 0; off >>= 1) {
            acc += __shfl_down_sync(0xFFFFFFFFu, acc, off);
            cnt += __shfl_down_sync(0xFFFFFFFFu, cnt, off);
        }
        if (lane == 0) {
            // Relaxed scalar accumulation — no fence, no L1 flush.
            atomicAdd(&g_sum, acc);
            atomicAdd(&g_cnt, cnt);

            // acq_rel ticket: release orders the adds above; acquire lets
            // the last arriver observe every block's adds.
            unsigned int ticket;
            asm volatile(
                "atom.acq_rel.gpu.global.add.u32 %0, [%1], %2;"
                : "=r"(ticket)
                : "l"(&g_ticket), "r"(1u)
                : "memory");

            if (ticket == gridDim.x - 1) {
                float        fsum = atomicAdd(&g_sum, 0.0f);
                unsigned int csum = atomicAdd(&g_cnt, 0u);
                d_out[0] = (csum == 0u) ? 0.0f : (fsum / (float)csum);
                // Self-clean for the next graph replay.
                atomicExch(&g_sum, 0.0f);
                atomicExch(&g_cnt, 0u);
                atomicExch(&g_ticket, 0u);
            }
        }
    }
}

extern "C" void kernel_launch(void* const* d_in, const int* in_sizes, int n_in,
                              void* d_out, int out_size)
{
    const float4* out_t = (const float4*)d_in[0];
    const float4* lbl0  = (const float4*)d_in[1];
    const float4* lbl1  = (const float4*)d_in[2];
    const int n  = in_sizes[0];   // 15,728,640 (divisible by 4)
    const int n4 = n >> 2;

    int blocks = NUM_BLOCKS;
    int max_blocks = (n4 + NUM_THREADS - 1) / NUM_THREADS;
    if (blocks > max_blocks) blocks = max_blocks;

    dlwm_fused_kernel<<<blocks, NUM_THREADS>>>(out_t, lbl0, lbl1, (float*)d_out, n4);
}